// round 3
// baseline (speedup 1.0000x reference)
#include <cuda_runtime.h>
#include <math.h>

#define BB 16
#define CCH 256
#define TT 576
#define NH 8
#define QSCALE 0.17677669529663687f
#define GN_EPS 1e-5f

__device__ float g_qkv[BB * 768 * TT];
__device__ float g_kt[BB * NH * TT * 32];
__device__ float g_vt[BB * NH * TT * 32];
__device__ float g_bd2[BB * NH * TT * 24];
__device__ float g_P[48 * 256];
__device__ float g_att[BB * TT * CCH];
__device__ float g_y[BB * CCH * TT];
__device__ float g_mu[BB * 16];
__device__ float g_rstd[BB * 16];

typedef unsigned long long ull;

__device__ __forceinline__ ull pk2(float lo, float hi) {
    ull r; asm("mov.b64 %0, {%1, %2};" : "=l"(r) : "f"(lo), "f"(hi)); return r;
}
__device__ __forceinline__ void upk2(float& lo, float& hi, ull v) {
    asm("mov.b64 {%0, %1}, %2;" : "=f"(lo), "=f"(hi) : "l"(v));
}
__device__ __forceinline__ void fma2(ull& d, ull a, ull b) {
    asm("fma.rn.f32x2 %0, %1, %2, %3;" : "=l"(d) : "l"(a), "l"(b), "l"(d));
}

__global__ void k0_prep(const float* __restrict__ rh_v, const float* __restrict__ rw_v) {
    int idx = blockIdx.x * 256 + threadIdx.x;
    int m = idx >> 8, rest = idx & 255;
    g_P[idx] = (m > 0) ? (rh_v[(m - 1) * 256 + rest] + rw_v[(m - 1) * 256 + rest]) : 0.f;
}

// ---------- k1: qkv GEMM, 64x64 tile, kk-packed f32x2 ----------
__global__ __launch_bounds__(256) void k1_qkv(const float* __restrict__ x,
                                              const float* __restrict__ w,
                                              const float* __restrict__ bias) {
    int b = blockIdx.z, o0 = blockIdx.y * 64, i0 = blockIdx.x * 64;
    __shared__ float As[64 * 20], Bs[64 * 20];
    int tid = threadIdx.x, tx = tid & 15, ty = tid >> 4;
    ull acc2[4][4];
#pragma unroll
    for (int r = 0; r < 4; r++)
#pragma unroll
        for (int s = 0; s < 4; s++) acc2[r][s] = 0ull;
    const float* xb = x + (size_t)b * CCH * TT;
    int rowA = tid >> 2, ccA = (tid & 3) * 4;
    int iiB = tid & 63, crB = (tid >> 6) * 4;

    for (int c0 = 0; c0 < 256; c0 += 16) {
        *(float4*)&As[rowA * 20 + ccA] = *(const float4*)&w[(o0 + rowA) * 256 + c0 + ccA];
        float4 bv;
        bv.x = xb[(c0 + crB + 0) * TT + i0 + iiB];
        bv.y = xb[(c0 + crB + 1) * TT + i0 + iiB];
        bv.z = xb[(c0 + crB + 2) * TT + i0 + iiB];
        bv.w = xb[(c0 + crB + 3) * TT + i0 + iiB];
        *(float4*)&Bs[iiB * 20 + crB] = bv;
        __syncthreads();
#pragma unroll
        for (int k4 = 0; k4 < 4; k4++) {
            ulonglong2 a2[4], b2[4];
#pragma unroll
            for (int r = 0; r < 4; r++) a2[r] = *(const ulonglong2*)&As[(ty * 4 + r) * 20 + k4 * 4];
#pragma unroll
            for (int s = 0; s < 4; s++) b2[s] = *(const ulonglong2*)&Bs[(tx * 4 + s) * 20 + k4 * 4];
#pragma unroll
            for (int r = 0; r < 4; r++)
#pragma unroll
                for (int s = 0; s < 4; s++) {
                    fma2(acc2[r][s], a2[r].x, b2[s].x);
                    fma2(acc2[r][s], a2[r].y, b2[s].y);
                }
        }
        __syncthreads();
    }
#pragma unroll
    for (int r = 0; r < 4; r++) {
        int o = o0 + ty * 4 + r;
        float bvv = bias[o];
        float ov[4];
#pragma unroll
        for (int s = 0; s < 4; s++) { float lo, hi; upk2(lo, hi, acc2[r][s]); ov[s] = lo + hi + bvv; }
        *(float4*)&g_qkv[((size_t)b * 768 + o) * TT + i0 + tx * 4] = make_float4(ov[0], ov[1], ov[2], ov[3]);
    }
}

__global__ void k1b_transpose() {
    int b = blockIdx.z, n = blockIdx.y, j0 = blockIdx.x * 32;
    __shared__ float tk[32][33], tv[32][33];
    int tx = threadIdx.x, ty = threadIdx.y;
#pragma unroll
    for (int r = 0; r < 4; r++) {
        int d = ty + 8 * r;
        tk[d][tx] = g_qkv[((size_t)b * 768 + 256 + n * 32 + d) * TT + j0 + tx];
        tv[d][tx] = g_qkv[((size_t)b * 768 + 512 + n * 32 + d) * TT + j0 + tx];
    }
    __syncthreads();
#pragma unroll
    for (int r = 0; r < 4; r++) {
        int jj = ty + 8 * r;
        size_t base = (((size_t)b * NH + n) * TT + j0 + jj) * 32 + tx;
        g_kt[base] = tk[tx][jj];
        g_vt[base] = tv[tx][jj];
    }
}

// ---------- k2: bd2, 32-i tiles, 288 blocks ----------
__global__ __launch_bounds__(256) void k2_bd2(const float* __restrict__ rh_k,
                                              const float* __restrict__ rw_k) {
    extern __shared__ float Rs[];   // [8][47][33]
    int b = blockIdx.y, i0 = blockIdx.x * 32;
    int tid = threadIdx.x;
    for (int idx = tid; idx < 8 * 47 * 32; idx += 256) {
        int n = idx / 1504, rem = idx % 1504, l = rem >> 5, d = rem & 31;
        Rs[(n * 47 + l) * 33 + d] = rh_k[(l * 8 + n) * 32 + d] + rw_k[(l * 8 + n) * 32 + d];
    }
    __syncthreads();
    int il = tid & 31, slot = tid >> 5;
    int ig = i0 + il;
    const float* qb = g_qkv + (size_t)b * 768 * TT;
    for (int idx = slot; idx < 192; idx += 8) {
        int n = idx / 24, c = idx % 24;
        int diff = c - ig;
        int fl = (diff >= 0) ? 0 : -((-diff + 47) / 48);
        int l = diff - 48 * fl;
        int iu = 12 + ig + fl;
        float acc = 0.f;
        if (l != 0) {
            const float* qr = qb + (size_t)(n * 32) * TT + iu;
            const float* rr = &Rs[(n * 47 + (l - 1)) * 33];
#pragma unroll
            for (int d = 0; d < 32; d++) acc += qr[(size_t)d * TT] * rr[d];
        }
        g_bd2[(((size_t)b * NH + n) * TT + ig) * 24 + c] = acc;
    }
}

// ---------- k3: fused attention, f32x2, no atomics ----------
__global__ __launch_bounds__(256) void k3_attn() {
    extern __shared__ float sm[];
    float* q_s  = sm;            // [8][16][32]   4096
    float* z_s  = sm + 4096;     // [8][32][20]   5120
    float* A_s  = sm + 9216;     // [8][16][25]   3200
    float* bd_s = sm + 12416;    // [8][16][24]   3072
    int b = blockIdx.y, i0 = blockIdx.x * 16;
    int tid = threadIdx.x, warp = tid >> 5, lane = tid & 31;

    {
        const float* qrow = g_qkv + ((size_t)b * 768 + tid) * TT + i0;
#pragma unroll
        for (int ii = 0; ii < 16; ii++) q_s[(warp * 16 + ii) * 32 + lane] = qrow[ii];
    }
    for (int idx = tid; idx < 8 * 16 * 24; idx += 256) {
        int n = idx / 384, r = idx % 384, ii = r / 24, c = r % 24;
        bd_s[idx] = g_bd2[(((size_t)b * NH + n) * TT + i0 + ii) * 24 + c];
    }
    for (int idx = tid; idx < 8 * 16 * 25; idx += 256) A_s[idx] = 0.f;

    ull acc2[8];
#pragma unroll
    for (int q = 0; q < 8; q++) acc2[q] = 0ull;
    __syncthreads();

    for (int jt = 0; jt < TT; jt += 32) {
        {   // logits: warp = head n, lane = j; packed along d
            int n = warp, j = jt + lane, c = j % 24;
            const ulonglong2* kp = (const ulonglong2*)(g_kt + (((size_t)b * NH + n) * TT + j) * 32);
            ulonglong2 kr[8];
#pragma unroll
            for (int q4 = 0; q4 < 8; q4++) kr[q4] = kp[q4];
#pragma unroll
            for (int ii = 0; ii < 16; ii++) {
                const ulonglong2* qv = (const ulonglong2*)&q_s[(n * 16 + ii) * 32];
                ull s2a = 0ull, s2b = 0ull;
#pragma unroll
                for (int q4 = 0; q4 < 8; q4++) {
                    ulonglong2 qq = qv[q4];
                    fma2(s2a, qq.x, kr[q4].x);
                    fma2(s2b, qq.y, kr[q4].y);
                }
                float a0, a1, b0, b1;
                upk2(a0, a1, s2a); upk2(b0, b1, s2b);
                z_s[(n * 32 + lane) * 20 + ii] = (a0 + a1) + (b0 + b1) + bd_s[(n * 16 + ii) * 24 + c];
            }
        }
        __syncthreads();
        {   // softmax over heads at each (i,j)
            int j = tid & 31, ibase = tid >> 5;
#pragma unroll
            for (int p = 0; p < 2; p++) {
                int i = ibase + 8 * p;
                float zz[8];
#pragma unroll
                for (int n = 0; n < 8; n++) zz[n] = z_s[(n * 32 + j) * 20 + i] * QSCALE;
                float mx = zz[0];
#pragma unroll
                for (int n = 1; n < 8; n++) mx = fmaxf(mx, zz[n]);
                float e[8], s = 0.f;
#pragma unroll
                for (int n = 0; n < 8; n++) { e[n] = __expf(zz[n] - mx); s += e[n]; }
                float inv = 1.f / s;
#pragma unroll
                for (int n = 0; n < 8; n++) z_s[(n * 32 + j) * 20 + i] = e[n] * inv;
            }
        }
        __syncthreads();
        {   // A-sums: owner RMW per head-warp; two steps dodge j/j+24 collision
            int n = warp, c = (jt + lane) % 24;
            if (lane < 24) {
#pragma unroll
                for (int ii = 0; ii < 16; ii++)
                    A_s[(n * 16 + ii) * 25 + c] += z_s[(n * 32 + lane) * 20 + ii];
            }
            __syncwarp();
            if (lane >= 24) {
#pragma unroll
                for (int ii = 0; ii < 16; ii++)
                    A_s[(n * 16 + ii) * 25 + c] += z_s[(n * 32 + lane) * 20 + ii];
            }
        }
        {   // attn @ v: warp = head n, lane = d; packed along ii
            int n = warp, d = lane;
            const float* vp = g_vt + (((size_t)b * NH + n) * TT + jt) * 32 + d;
#pragma unroll 4
            for (int jj = 0; jj < 32; jj++) {
                ull vv = pk2(vp[jj * 32], vp[jj * 32]);
                const ull* ap = (const ull*)&z_s[(n * 32 + jj) * 20];
#pragma unroll
                for (int q = 0; q < 8; q++) fma2(acc2[q], ap[q], vv);
            }
        }
        __syncthreads();
    }
    {   // epilogue: positional-value term
        int n = warp, d = lane;
        float accv[16];
#pragma unroll
        for (int q = 0; q < 8; q++) upk2(accv[2 * q], accv[2 * q + 1], acc2[q]);
#pragma unroll
        for (int ii = 0; ii < 16; ii++) {
            int ig = i0 + ii;
            float o2 = 0.f;
#pragma unroll
            for (int c = 0; c < 24; c++) {
                int m = (c - ig) % 48; if (m < 0) m += 48;
                o2 += A_s[(n * 16 + ii) * 25 + c] * g_P[m * 256 + n * 32 + d];
            }
            g_att[((size_t)b * TT + ig) * CCH + n * 32 + d] = accv[ii] + o2;
        }
    }
}

// ---------- k4: fc GEMM + residual ----------
__global__ __launch_bounds__(256) void k4_fc(const float* __restrict__ x,
                                             const float* __restrict__ w,
                                             const float* __restrict__ bias) {
    int b = blockIdx.z, o0 = blockIdx.y * 64, i0 = blockIdx.x * 64;
    __shared__ float As[64 * 20], Bs[64 * 20];
    int tid = threadIdx.x, tx = tid & 15, ty = tid >> 4;
    ull acc2[4][4];
#pragma unroll
    for (int r = 0; r < 4; r++)
#pragma unroll
        for (int s = 0; s < 4; s++) acc2[r][s] = 0ull;
    const float* att = g_att + (size_t)b * TT * CCH;
    int rowA = tid >> 2, ccA = (tid & 3) * 4;

    for (int c0 = 0; c0 < 256; c0 += 16) {
        *(float4*)&As[rowA * 20 + ccA] = *(const float4*)&w[(o0 + rowA) * 256 + c0 + ccA];
        *(float4*)&Bs[rowA * 20 + ccA] = *(const float4*)&att[(i0 + rowA) * 256 + c0 + ccA];
        __syncthreads();
#pragma unroll
        for (int k4 = 0; k4 < 4; k4++) {
            ulonglong2 a2[4], b2[4];
#pragma unroll
            for (int r = 0; r < 4; r++) a2[r] = *(const ulonglong2*)&As[(ty * 4 + r) * 20 + k4 * 4];
#pragma unroll
            for (int s = 0; s < 4; s++) b2[s] = *(const ulonglong2*)&Bs[(tx * 4 + s) * 20 + k4 * 4];
#pragma unroll
            for (int r = 0; r < 4; r++)
#pragma unroll
                for (int s = 0; s < 4; s++) {
                    fma2(acc2[r][s], a2[r].x, b2[s].x);
                    fma2(acc2[r][s], a2[r].y, b2[s].y);
                }
        }
        __syncthreads();
    }
#pragma unroll
    for (int r = 0; r < 4; r++) {
        int o = o0 + ty * 4 + r;
        float bvv = bias[o];
        float4 xv = *(const float4*)&x[((size_t)b * CCH + o) * TT + i0 + tx * 4];
        float ov[4];
#pragma unroll
        for (int s = 0; s < 4; s++) { float lo, hi; upk2(lo, hi, acc2[r][s]); ov[s] = lo + hi + bvv; }
        *(float4*)&g_y[((size_t)b * CCH + o) * TT + i0 + tx * 4] =
            make_float4(ov[0] + xv.x, ov[1] + xv.y, ov[2] + xv.z, ov[3] + xv.w);
    }
}

__global__ void k5_gnstats() {
    int bid = blockIdx.x, b = bid >> 4, g = bid & 15;
    const float* yp = g_y + ((size_t)(b * CCH + g * 16)) * TT;
    int tid = threadIdx.x;
    float s = 0.f, sq = 0.f;
    for (int idx = tid; idx < 16 * TT; idx += 256) { float v = yp[idx]; s += v; sq += v * v; }
#pragma unroll
    for (int off = 16; off > 0; off >>= 1) {
        s  += __shfl_down_sync(0xffffffffu, s, off);
        sq += __shfl_down_sync(0xffffffffu, sq, off);
    }
    __shared__ float rs[8], rq[8];
    if ((tid & 31) == 0) { rs[tid >> 5] = s; rq[tid >> 5] = sq; }
    __syncthreads();
    if (tid == 0) {
        float S = 0.f, Q = 0.f;
#pragma unroll
        for (int w = 0; w < 8; w++) { S += rs[w]; Q += rq[w]; }
        float mu = S / 9216.f;
        float var = Q / 9216.f - mu * mu;
        g_mu[bid] = mu;
        g_rstd[bid] = rsqrtf(var + GN_EPS);
    }
}

__global__ void k6_gnapply(float* __restrict__ out, const float* __restrict__ gw,
                           const float* __restrict__ gb) {
    int idx = blockIdx.x * 256 + threadIdx.x;
    int o = (idx / TT) & 255;
    int b = idx / (TT * CCH);
    float mu = g_mu[b * 16 + (o >> 4)], rstd = g_rstd[b * 16 + (o >> 4)];
    out[idx] = (g_y[idx] - mu) * rstd * gw[o] + gb[o];
}

extern "C" void kernel_launch(void* const* d_in, const int* in_sizes, int n_in,
                              void* d_out, int out_size) {
    const float* x     = (const float*)d_in[0];
    const float* qkv_w = (const float*)d_in[1];
    const float* qkv_b = (const float*)d_in[2];
    const float* rh_k  = (const float*)d_in[3];
    const float* rw_k  = (const float*)d_in[4];
    const float* rh_v  = (const float*)d_in[5];
    const float* rw_v  = (const float*)d_in[6];
    const float* fc_w  = (const float*)d_in[7];
    const float* fc_b  = (const float*)d_in[8];
    const float* gn_w  = (const float*)d_in[9];
    const float* gn_b  = (const float*)d_in[10];
    float* out = (float*)d_out;

    cudaFuncSetAttribute(k2_bd2, cudaFuncAttributeMaxDynamicSharedMemorySize, 49632);
    cudaFuncSetAttribute(k3_attn, cudaFuncAttributeMaxDynamicSharedMemorySize, 61952);

    k0_prep<<<48, 256>>>(rh_v, rw_v);
    k1_qkv<<<dim3(9, 12, BB), 256>>>(x, qkv_w, qkv_b);
    k1b_transpose<<<dim3(18, NH, BB), dim3(32, 8)>>>();
    k2_bd2<<<dim3(18, BB), 256, 49632>>>(rh_k, rw_k);
    k3_attn<<<dim3(36, BB), 256, 61952>>>();
    k4_fc<<<dim3(9, 4, BB), 256>>>(x, fc_w, fc_b);
    k5_gnstats<<<256, 256>>>();
    k6_gnapply<<<9216, 256>>>(out, gn_w, gn_b);
}

// round 4
// speedup vs baseline: 1.2023x; 1.2023x over previous
#include <cuda_runtime.h>
#include <math.h>

#define BB 16
#define CCH 256
#define TT 576
#define NH 8
#define QSCALE 0.17677669529663687f
#define GN_EPS 1e-5f

__device__ float g_qkv[BB * 768 * TT];
__device__ float g_qt[BB * NH * TT * 32];
__device__ float g_kt[BB * NH * TT * 32];
__device__ float g_vt[BB * NH * TT * 32];
__device__ float g_bd2[BB * NH * TT * 24];
__device__ float g_P[48 * 256];
__device__ float g_R[NH * 47 * 32];
__device__ float g_att[BB * TT * CCH];
__device__ float g_y[BB * CCH * TT];
__device__ float g_mu[BB * 16];
__device__ float g_rstd[BB * 16];

// ---------- k0: P table (48x256) + R table (8x47x32) ----------
__global__ void k0_prep(const float* __restrict__ rh_v, const float* __restrict__ rw_v,
                        const float* __restrict__ rh_k, const float* __restrict__ rw_k) {
    int bx = blockIdx.x, tid = threadIdx.x;
    if (bx < 48) {
        int idx = bx * 256 + tid;
        int m = idx >> 8, rest = idx & 255;
        g_P[idx] = (m > 0) ? (rh_v[(m - 1) * 256 + rest] + rw_v[(m - 1) * 256 + rest]) : 0.f;
    } else {
        int l = bx - 48;                 // 0..46
        int n = tid >> 5, d = tid & 31;
        g_R[(n * 47 + l) * 32 + d] = rh_k[(l * 8 + n) * 32 + d] + rw_k[(l * 8 + n) * 32 + d];
    }
}

// ---------- k1: qkv GEMM 64x64 tile (plain FFMA, R2-proven) ----------
__global__ __launch_bounds__(256) void k1_qkv(const float* __restrict__ x,
                                              const float* __restrict__ w,
                                              const float* __restrict__ bias) {
    int b = blockIdx.z, o0 = blockIdx.y * 64, i0 = blockIdx.x * 64;
    __shared__ float As[16][68], Bs[16][68];
    float acc[4][4] = {};
    int tid = threadIdx.x, tx = tid % 16, ty = tid / 16;
    const float* xb = x + (size_t)b * CCH * TT;
    for (int c0 = 0; c0 < 256; c0 += 16) {
        int row = tid >> 2, cc = (tid & 3) * 4;
        float4 wv = *(const float4*)&w[(o0 + row) * 256 + c0 + cc];
        As[cc + 0][row] = wv.x; As[cc + 1][row] = wv.y;
        As[cc + 2][row] = wv.z; As[cc + 3][row] = wv.w;
        int cr = tid >> 4, i4 = (tid & 15) * 4;
        *(float4*)&Bs[cr][i4] = *(const float4*)&xb[(c0 + cr) * TT + i0 + i4];
        __syncthreads();
#pragma unroll
        for (int kk = 0; kk < 16; kk++) {
            float a[4], bv[4];
            *(float4*)a  = *(const float4*)&As[kk][ty * 4];
            *(float4*)bv = *(const float4*)&Bs[kk][tx * 4];
#pragma unroll
            for (int r = 0; r < 4; r++)
#pragma unroll
                for (int s = 0; s < 4; s++) acc[r][s] += a[r] * bv[s];
        }
        __syncthreads();
    }
#pragma unroll
    for (int r = 0; r < 4; r++) {
        int o = o0 + ty * 4 + r;
        float bv = bias[o];
        *(float4*)&g_qkv[((size_t)b * 768 + o) * TT + i0 + tx * 4] =
            make_float4(acc[r][0] + bv, acc[r][1] + bv, acc[r][2] + bv, acc[r][3] + bv);
    }
}

// ---------- k1b: transpose q,k,v into [b][n][t][d] ----------
__global__ void k1b_transpose() {
    int b = blockIdx.z, n = blockIdx.y, j0 = blockIdx.x * 32;
    __shared__ float tq[32][33], tk[32][33], tv[32][33];
    int tx = threadIdx.x, ty = threadIdx.y;
#pragma unroll
    for (int r = 0; r < 4; r++) {
        int d = ty + 8 * r;
        tq[d][tx] = g_qkv[((size_t)b * 768 +       n * 32 + d) * TT + j0 + tx];
        tk[d][tx] = g_qkv[((size_t)b * 768 + 256 + n * 32 + d) * TT + j0 + tx];
        tv[d][tx] = g_qkv[((size_t)b * 768 + 512 + n * 32 + d) * TT + j0 + tx];
    }
    __syncthreads();
#pragma unroll
    for (int r = 0; r < 4; r++) {
        int jj = ty + 8 * r;
        size_t base = (((size_t)b * NH + n) * TT + j0 + jj) * 32 + tx;
        g_qt[base] = tq[tx][jj];
        g_kt[base] = tk[tx][jj];
        g_vt[base] = tv[tx][jj];
    }
}

// ---------- k2: bd2 via coalesced qt/R dots, no smem ----------
__global__ __launch_bounds__(256) void k2_bd2() {
    int b = blockIdx.y, i0 = blockIdx.x * 32;
    int tid = threadIdx.x;
    int il = tid & 31, slot = tid >> 5;
    int ig = i0 + il;
    for (int idx = slot; idx < 192; idx += 8) {
        int n = idx / 24, c = idx % 24;
        int diff = c - ig;
        int fl = (diff >= 0) ? 0 : -((-diff + 47) / 48);
        int l = diff - 48 * fl;
        int iu = 12 + ig + fl;
        float acc = 0.f;
        if (l != 0) {
            const float4* qr = (const float4*)&g_qt[(((size_t)b * NH + n) * TT + iu) * 32];
            const float4* rr = (const float4*)&g_R[(n * 47 + l - 1) * 32];
#pragma unroll
            for (int q4 = 0; q4 < 8; q4++) {
                float4 a = qr[q4], r = rr[q4];
                acc += a.x * r.x + a.y * r.y + a.z * r.z + a.w * r.w;
            }
        }
        g_bd2[(((size_t)b * NH + n) * TT + ig) * 24 + c] = acc;
    }
}

// ---------- k3: fused attention (plain FFMA, owner-RMW A-sums) ----------
__global__ __launch_bounds__(256) void k3_attn() {
    extern __shared__ float sm[];
    float* q_s  = sm;            // [8][16][32]   4096
    float* z_s  = sm + 4096;     // [8][32][20]   5120
    float* A_s  = sm + 9216;     // [8][16][25]   3200
    float* bd_s = sm + 12416;    // [8][16][24]   3072
    int b = blockIdx.y, i0 = blockIdx.x * 16;
    int tid = threadIdx.x, warp = tid >> 5, lane = tid & 31;

    {   // coalesced q tile load from g_qt
        const float* qt = g_qt + (((size_t)b * NH + warp) * TT + i0) * 32;
#pragma unroll
        for (int ii = 0; ii < 16; ii++) q_s[(warp * 16 + ii) * 32 + lane] = qt[ii * 32 + lane];
    }
    for (int idx = tid; idx < 8 * 16 * 24; idx += 256) {
        int n = idx / 384, r = idx % 384, ii = r / 24, c = r % 24;
        bd_s[idx] = g_bd2[(((size_t)b * NH + n) * TT + i0 + ii) * 24 + c];
    }
    for (int idx = tid; idx < 8 * 16 * 25; idx += 256) A_s[idx] = 0.f;

    float acc[16];
#pragma unroll
    for (int ii = 0; ii < 16; ii++) acc[ii] = 0.f;
    __syncthreads();

    for (int jt = 0; jt < TT; jt += 32) {
        {   // logits: warp = head n, lane = j
            int n = warp, j = jt + lane, c = j % 24;
            const float4* kp = (const float4*)(g_kt + (((size_t)b * NH + n) * TT + j) * 32);
            float4 kr[8];
#pragma unroll
            for (int q4 = 0; q4 < 8; q4++) kr[q4] = kp[q4];
#pragma unroll
            for (int ii = 0; ii < 16; ii++) {
                const float4* qv = (const float4*)&q_s[(n * 16 + ii) * 32];
                float s = 0.f;
#pragma unroll
                for (int q4 = 0; q4 < 8; q4++) {
                    float4 qq = qv[q4];
                    s += qq.x * kr[q4].x + qq.y * kr[q4].y + qq.z * kr[q4].z + qq.w * kr[q4].w;
                }
                z_s[(n * 32 + lane) * 20 + ii] = s + bd_s[(n * 16 + ii) * 24 + c];
            }
        }
        __syncthreads();
        {   // softmax over heads at each (i,j)
            int j = tid & 31, ibase = tid >> 5;
#pragma unroll
            for (int p = 0; p < 2; p++) {
                int i = ibase + 8 * p;
                float zz[8];
#pragma unroll
                for (int n = 0; n < 8; n++) zz[n] = z_s[(n * 32 + j) * 20 + i] * QSCALE;
                float mx = zz[0];
#pragma unroll
                for (int n = 1; n < 8; n++) mx = fmaxf(mx, zz[n]);
                float e[8], s = 0.f;
#pragma unroll
                for (int n = 0; n < 8; n++) { e[n] = __expf(zz[n] - mx); s += e[n]; }
                float inv = 1.f / s;
#pragma unroll
                for (int n = 0; n < 8; n++) z_s[(n * 32 + j) * 20 + i] = e[n] * inv;
            }
        }
        __syncthreads();
        {   // A-sums: owner RMW per head-warp (two steps: j and j+24 share c)
            int n = warp, c = (jt + lane) % 24;
            if (lane < 24) {
#pragma unroll
                for (int ii = 0; ii < 16; ii++)
                    A_s[(n * 16 + ii) * 25 + c] += z_s[(n * 32 + lane) * 20 + ii];
            }
            __syncwarp();
            if (lane >= 24) {
#pragma unroll
                for (int ii = 0; ii < 16; ii++)
                    A_s[(n * 16 + ii) * 25 + c] += z_s[(n * 32 + lane) * 20 + ii];
            }
        }
        {   // attn @ v: warp = head n, lane = d
            int n = warp, d = lane;
            const float* vp = g_vt + (((size_t)b * NH + n) * TT + jt) * 32 + d;
#pragma unroll 4
            for (int jj = 0; jj < 32; jj++) {
                float v = vp[jj * 32];
                const float4* ap = (const float4*)&z_s[(n * 32 + jj) * 20];
#pragma unroll
                for (int q4 = 0; q4 < 4; q4++) {
                    float4 a = ap[q4];
                    acc[q4 * 4 + 0] += a.x * v; acc[q4 * 4 + 1] += a.y * v;
                    acc[q4 * 4 + 2] += a.z * v; acc[q4 * 4 + 3] += a.w * v;
                }
            }
        }
        __syncthreads();
    }
    {   // epilogue: positional-value term
        int n = warp, d = lane;
#pragma unroll
        for (int ii = 0; ii < 16; ii++) {
            int ig = i0 + ii;
            float o2 = 0.f;
#pragma unroll
            for (int c = 0; c < 24; c++) {
                int m = (c - ig) % 48; if (m < 0) m += 48;
                o2 += A_s[(n * 16 + ii) * 25 + c] * g_P[m * 256 + n * 32 + d];
            }
            g_att[((size_t)b * TT + ig) * CCH + n * 32 + d] = acc[ii] + o2;
        }
    }
}

// ---------- k4: fc GEMM + residual (plain FFMA, R2-proven) ----------
__global__ __launch_bounds__(256) void k4_fc(const float* __restrict__ x,
                                             const float* __restrict__ w,
                                             const float* __restrict__ bias) {
    int b = blockIdx.z, o0 = blockIdx.y * 64, i0 = blockIdx.x * 64;
    __shared__ float As[16][68], Bs[16][68];
    float acc[4][4] = {};
    int tid = threadIdx.x, tx = tid % 16, ty = tid / 16;
    const float* att = g_att + (size_t)b * TT * CCH;
    for (int c0 = 0; c0 < 256; c0 += 16) {
        int row = tid >> 2, cc = (tid & 3) * 4;
        float4 wv = *(const float4*)&w[(o0 + row) * 256 + c0 + cc];
        As[cc + 0][row] = wv.x; As[cc + 1][row] = wv.y;
        As[cc + 2][row] = wv.z; As[cc + 3][row] = wv.w;
        float4 av = *(const float4*)&att[(i0 + row) * 256 + c0 + cc];
        Bs[cc + 0][row] = av.x; Bs[cc + 1][row] = av.y;
        Bs[cc + 2][row] = av.z; Bs[cc + 3][row] = av.w;
        __syncthreads();
#pragma unroll
        for (int kk = 0; kk < 16; kk++) {
            float a[4], bv[4];
            *(float4*)a  = *(const float4*)&As[kk][ty * 4];
            *(float4*)bv = *(const float4*)&Bs[kk][tx * 4];
#pragma unroll
            for (int r = 0; r < 4; r++)
#pragma unroll
                for (int s = 0; s < 4; s++) acc[r][s] += a[r] * bv[s];
        }
        __syncthreads();
    }
#pragma unroll
    for (int r = 0; r < 4; r++) {
        int o = o0 + ty * 4 + r;
        float bv = bias[o];
        float4 xv = *(const float4*)&x[((size_t)b * CCH + o) * TT + i0 + tx * 4];
        *(float4*)&g_y[((size_t)b * CCH + o) * TT + i0 + tx * 4] =
            make_float4(acc[r][0] + bv + xv.x, acc[r][1] + bv + xv.y,
                        acc[r][2] + bv + xv.z, acc[r][3] + bv + xv.w);
    }
}

__global__ void k5_gnstats() {
    int bid = blockIdx.x, b = bid >> 4, g = bid & 15;
    const float* yp = g_y + ((size_t)(b * CCH + g * 16)) * TT;
    int tid = threadIdx.x;
    float s = 0.f, sq = 0.f;
    for (int idx = tid; idx < 16 * TT; idx += 256) { float v = yp[idx]; s += v; sq += v * v; }
#pragma unroll
    for (int off = 16; off > 0; off >>= 1) {
        s  += __shfl_down_sync(0xffffffffu, s, off);
        sq += __shfl_down_sync(0xffffffffu, sq, off);
    }
    __shared__ float rs[8], rq[8];
    if ((tid & 31) == 0) { rs[tid >> 5] = s; rq[tid >> 5] = sq; }
    __syncthreads();
    if (tid == 0) {
        float S = 0.f, Q = 0.f;
#pragma unroll
        for (int w = 0; w < 8; w++) { S += rs[w]; Q += rq[w]; }
        float mu = S / 9216.f;
        float var = Q / 9216.f - mu * mu;
        g_mu[bid] = mu;
        g_rstd[bid] = rsqrtf(var + GN_EPS);
    }
}

__global__ void k6_gnapply(float* __restrict__ out, const float* __restrict__ gw,
                           const float* __restrict__ gb) {
    int idx = blockIdx.x * 256 + threadIdx.x;
    int o = (idx / TT) & 255;
    int b = idx / (TT * CCH);
    float mu = g_mu[b * 16 + (o >> 4)], rstd = g_rstd[b * 16 + (o >> 4)];
    out[idx] = (g_y[idx] - mu) * rstd * gw[o] + gb[o];
}

extern "C" void kernel_launch(void* const* d_in, const int* in_sizes, int n_in,
                              void* d_out, int out_size) {
    const float* x     = (const float*)d_in[0];
    const float* qkv_w = (const float*)d_in[1];
    const float* qkv_b = (const float*)d_in[2];
    const float* rh_k  = (const float*)d_in[3];
    const float* rw_k  = (const float*)d_in[4];
    const float* rh_v  = (const float*)d_in[5];
    const float* rw_v  = (const float*)d_in[6];
    const float* fc_w  = (const float*)d_in[7];
    const float* fc_b  = (const float*)d_in[8];
    const float* gn_w  = (const float*)d_in[9];
    const float* gn_b  = (const float*)d_in[10];
    float* out = (float*)d_out;

    cudaFuncSetAttribute(k3_attn, cudaFuncAttributeMaxDynamicSharedMemorySize, 61952);

    k0_prep<<<95, 256>>>(rh_v, rw_v, rh_k, rw_k);
    k1_qkv<<<dim3(9, 12, BB), 256>>>(x, qkv_w, qkv_b);
    k1b_transpose<<<dim3(18, NH, BB), dim3(32, 8)>>>();
    k2_bd2<<<dim3(18, BB), 256>>>();
    k3_attn<<<dim3(36, BB), 256, 61952>>>();
    k4_fc<<<dim3(9, 4, BB), 256>>>(x, fc_w, fc_b);
    k5_gnstats<<<256, 256>>>();
    k6_gnapply<<<9216, 256>>>(out, gn_w, gn_b);
}

// round 5
// speedup vs baseline: 1.3459x; 1.1195x over previous
#include <cuda_runtime.h>
#include <math.h>

#define BB 16
#define CCH 256
#define TT 576
#define NH 8
#define QSCALE 0.17677669529663687f
#define GN_EPS 1e-5f

__device__ float g_qkv[BB * 768 * TT];
__device__ float g_qt[BB * NH * TT * 32];
__device__ float g_kt[BB * NH * TT * 32];
__device__ float g_vt[BB * NH * TT * 32];
__device__ float g_bd2[BB * NH * TT * 24];
__device__ float g_P[48 * 256];
__device__ float g_R[NH * 47 * 32];
__device__ float g_att[BB * TT * CCH];
__device__ float g_y[BB * CCH * TT];
__device__ float g_mu[BB * 16];
__device__ float g_rstd[BB * 16];

// ---------- k0: P table (48x256) + R table (8x47x32) ----------
__global__ void k0_prep(const float* __restrict__ rh_v, const float* __restrict__ rw_v,
                        const float* __restrict__ rh_k, const float* __restrict__ rw_k) {
    int bx = blockIdx.x, tid = threadIdx.x;
    if (bx < 48) {
        int idx = bx * 256 + tid;
        int m = idx >> 8, rest = idx & 255;
        g_P[idx] = (m > 0) ? (rh_v[(m - 1) * 256 + rest] + rw_v[(m - 1) * 256 + rest]) : 0.f;
    } else {
        int l = bx - 48;                 // 0..46
        int n = tid >> 5, d = tid & 31;
        g_R[(n * 47 + l) * 32 + d] = rh_k[(l * 8 + n) * 32 + d] + rw_k[(l * 8 + n) * 32 + d];
    }
}

// ---------- k1: qkv GEMM 64x64 tile ----------
__global__ __launch_bounds__(256) void k1_qkv(const float* __restrict__ x,
                                              const float* __restrict__ w,
                                              const float* __restrict__ bias) {
    int b = blockIdx.z, o0 = blockIdx.y * 64, i0 = blockIdx.x * 64;
    __shared__ float As[16][68], Bs[16][68];
    float acc[4][4] = {};
    int tid = threadIdx.x, tx = tid % 16, ty = tid / 16;
    const float* xb = x + (size_t)b * CCH * TT;
    for (int c0 = 0; c0 < 256; c0 += 16) {
        int row = tid >> 2, cc = (tid & 3) * 4;
        float4 wv = *(const float4*)&w[(o0 + row) * 256 + c0 + cc];
        As[cc + 0][row] = wv.x; As[cc + 1][row] = wv.y;
        As[cc + 2][row] = wv.z; As[cc + 3][row] = wv.w;
        int cr = tid >> 4, i4 = (tid & 15) * 4;
        *(float4*)&Bs[cr][i4] = *(const float4*)&xb[(c0 + cr) * TT + i0 + i4];
        __syncthreads();
#pragma unroll
        for (int kk = 0; kk < 16; kk++) {
            float a[4], bv[4];
            *(float4*)a  = *(const float4*)&As[kk][ty * 4];
            *(float4*)bv = *(const float4*)&Bs[kk][tx * 4];
#pragma unroll
            for (int r = 0; r < 4; r++)
#pragma unroll
                for (int s = 0; s < 4; s++) acc[r][s] += a[r] * bv[s];
        }
        __syncthreads();
    }
#pragma unroll
    for (int r = 0; r < 4; r++) {
        int o = o0 + ty * 4 + r;
        float bv = bias[o];
        *(float4*)&g_qkv[((size_t)b * 768 + o) * TT + i0 + tx * 4] =
            make_float4(acc[r][0] + bv, acc[r][1] + bv, acc[r][2] + bv, acc[r][3] + bv);
    }
}

// ---------- k1b: transpose q,k,v into [b][n][t][d] ----------
__global__ void k1b_transpose() {
    int b = blockIdx.z, n = blockIdx.y, j0 = blockIdx.x * 32;
    __shared__ float tq[32][33], tk[32][33], tv[32][33];
    int tx = threadIdx.x, ty = threadIdx.y;
#pragma unroll
    for (int r = 0; r < 4; r++) {
        int d = ty + 8 * r;
        tq[d][tx] = g_qkv[((size_t)b * 768 +       n * 32 + d) * TT + j0 + tx];
        tk[d][tx] = g_qkv[((size_t)b * 768 + 256 + n * 32 + d) * TT + j0 + tx];
        tv[d][tx] = g_qkv[((size_t)b * 768 + 512 + n * 32 + d) * TT + j0 + tx];
    }
    __syncthreads();
#pragma unroll
    for (int r = 0; r < 4; r++) {
        int jj = ty + 8 * r;
        size_t base = (((size_t)b * NH + n) * TT + j0 + jj) * 32 + tx;
        g_qt[base] = tq[tx][jj];
        g_kt[base] = tk[tx][jj];
        g_vt[base] = tv[tx][jj];
    }
}

// ---------- k2: bd2 — R2-proven coalesced pattern + 2-way ILP ----------
__global__ __launch_bounds__(256) void k2_bd2() {
    extern __shared__ float Rs[];   // [8][47][33]
    int b = blockIdx.y, i0 = blockIdx.x * 32;
    int tid = threadIdx.x;
    for (int idx = tid; idx < 8 * 47 * 32; idx += 256) {
        int n = idx / 1504, rem = idx % 1504, l = rem >> 5, d = rem & 31;
        Rs[(n * 47 + l) * 33 + d] = g_R[idx];          // coalesced
    }
    __syncthreads();
    int il = tid & 31, slot = tid >> 5;
    int ig = i0 + il;
    const float* qb = g_qkv + (size_t)b * 768 * TT;
    for (int idx = slot; idx < 192; idx += 16) {
        int idx1 = idx + 8;
        int n0 = idx / 24,  c0 = idx % 24;
        int n1 = idx1 / 24, c1 = idx1 % 24;
        int df0 = c0 - ig, df1 = c1 - ig;
        int fl0 = (df0 >= 0) ? 0 : -((-df0 + 47) / 48);
        int fl1 = (df1 >= 0) ? 0 : -((-df1 + 47) / 48);
        int l0 = df0 - 48 * fl0, l1 = df1 - 48 * fl1;
        int iu0 = 12 + ig + fl0, iu1 = 12 + ig + fl1;
        const float* q0 = qb + (size_t)(n0 * 32) * TT + iu0;
        const float* q1 = qb + (size_t)(n1 * 32) * TT + iu1;
        const float* r0 = &Rs[(n0 * 47 + (l0 > 0 ? l0 - 1 : 0)) * 33];
        const float* r1 = &Rs[(n1 * 47 + (l1 > 0 ? l1 - 1 : 0)) * 33];
        float a0 = 0.f, a1 = 0.f;
#pragma unroll
        for (int d = 0; d < 32; d++) {
            a0 += q0[(size_t)d * TT] * r0[d];   // LDG coalesced across lanes (iu consecutive)
            a1 += q1[(size_t)d * TT] * r1[d];   // LDS conflict-free (stride 33)
        }
        if (l0 == 0) a0 = 0.f;
        if (l1 == 0) a1 = 0.f;
        g_bd2[(((size_t)b * NH + n0) * TT + ig) * 24 + c0] = a0;
        g_bd2[(((size_t)b * NH + n1) * TT + ig) * 24 + c1] = a1;
    }
}

// ---------- k3: fused attention ----------
__global__ __launch_bounds__(256) void k3_attn() {
    extern __shared__ float sm[];
    float* q_s  = sm;            // [8][16][32]   4096
    float* z_s  = sm + 4096;     // [8][32][20]   5120
    float* A_s  = sm + 9216;     // [8][16][25]   3200
    float* bd_s = sm + 12416;    // [8][16][24]   3072
    int b = blockIdx.y, i0 = blockIdx.x * 16;
    int tid = threadIdx.x, warp = tid >> 5, lane = tid & 31;

    {   // coalesced q tile load from g_qt
        const float* qt = g_qt + (((size_t)b * NH + warp) * TT + i0) * 32;
#pragma unroll
        for (int ii = 0; ii < 16; ii++) q_s[(warp * 16 + ii) * 32 + lane] = qt[ii * 32 + lane];
    }
    for (int idx = tid; idx < 8 * 16 * 24; idx += 256) {
        int n = idx / 384, r = idx % 384, ii = r / 24, c = r % 24;
        bd_s[idx] = g_bd2[(((size_t)b * NH + n) * TT + i0 + ii) * 24 + c];
    }
    for (int idx = tid; idx < 8 * 16 * 25; idx += 256) A_s[idx] = 0.f;

    float acc[16];
#pragma unroll
    for (int ii = 0; ii < 16; ii++) acc[ii] = 0.f;
    __syncthreads();

    for (int jt = 0; jt < TT; jt += 32) {
        {   // logits: warp = head n, lane = j
            int n = warp, j = jt + lane, c = j % 24;
            const float4* kp = (const float4*)(g_kt + (((size_t)b * NH + n) * TT + j) * 32);
            float4 kr[8];
#pragma unroll
            for (int q4 = 0; q4 < 8; q4++) kr[q4] = kp[q4];
#pragma unroll
            for (int ii = 0; ii < 16; ii++) {
                const float4* qv = (const float4*)&q_s[(n * 16 + ii) * 32];
                float s = 0.f;
#pragma unroll
                for (int q4 = 0; q4 < 8; q4++) {
                    float4 qq = qv[q4];
                    s += qq.x * kr[q4].x + qq.y * kr[q4].y + qq.z * kr[q4].z + qq.w * kr[q4].w;
                }
                z_s[(n * 32 + lane) * 20 + ii] = s + bd_s[(n * 16 + ii) * 24 + c];
            }
        }
        __syncthreads();
        {   // softmax over heads at each (i,j)
            int j = tid & 31, ibase = tid >> 5;
#pragma unroll
            for (int p = 0; p < 2; p++) {
                int i = ibase + 8 * p;
                float zz[8];
#pragma unroll
                for (int n = 0; n < 8; n++) zz[n] = z_s[(n * 32 + j) * 20 + i] * QSCALE;
                float mx = zz[0];
#pragma unroll
                for (int n = 1; n < 8; n++) mx = fmaxf(mx, zz[n]);
                float e[8], s = 0.f;
#pragma unroll
                for (int n = 0; n < 8; n++) { e[n] = __expf(zz[n] - mx); s += e[n]; }
                float inv = 1.f / s;
#pragma unroll
                for (int n = 0; n < 8; n++) z_s[(n * 32 + j) * 20 + i] = e[n] * inv;
            }
        }
        __syncthreads();
        {   // A-sums: owner RMW per head-warp (two steps: j and j+24 share c)
            int n = warp, c = (jt + lane) % 24;
            if (lane < 24) {
#pragma unroll
                for (int ii = 0; ii < 16; ii++)
                    A_s[(n * 16 + ii) * 25 + c] += z_s[(n * 32 + lane) * 20 + ii];
            }
            __syncwarp();
            if (lane >= 24) {
#pragma unroll
                for (int ii = 0; ii < 16; ii++)
                    A_s[(n * 16 + ii) * 25 + c] += z_s[(n * 32 + lane) * 20 + ii];
            }
        }
        {   // attn @ v: warp = head n, lane = d
            int n = warp, d = lane;
            const float* vp = g_vt + (((size_t)b * NH + n) * TT + jt) * 32 + d;
#pragma unroll 4
            for (int jj = 0; jj < 32; jj++) {
                float v = vp[jj * 32];
                const float4* ap = (const float4*)&z_s[(n * 32 + jj) * 20];
#pragma unroll
                for (int q4 = 0; q4 < 4; q4++) {
                    float4 a = ap[q4];
                    acc[q4 * 4 + 0] += a.x * v; acc[q4 * 4 + 1] += a.y * v;
                    acc[q4 * 4 + 2] += a.z * v; acc[q4 * 4 + 3] += a.w * v;
                }
            }
        }
        __syncthreads();
    }
    {   // epilogue: positional-value term
        int n = warp, d = lane;
#pragma unroll
        for (int ii = 0; ii < 16; ii++) {
            int ig = i0 + ii;
            float o2 = 0.f;
#pragma unroll
            for (int c = 0; c < 24; c++) {
                int m = (c - ig) % 48; if (m < 0) m += 48;
                o2 += A_s[(n * 16 + ii) * 25 + c] * g_P[m * 256 + n * 32 + d];
            }
            g_att[((size_t)b * TT + ig) * CCH + n * 32 + d] = acc[ii] + o2;
        }
    }
}

// ---------- k4: fc GEMM + residual ----------
__global__ __launch_bounds__(256) void k4_fc(const float* __restrict__ x,
                                             const float* __restrict__ w,
                                             const float* __restrict__ bias) {
    int b = blockIdx.z, o0 = blockIdx.y * 64, i0 = blockIdx.x * 64;
    __shared__ float As[16][68], Bs[16][68];
    float acc[4][4] = {};
    int tid = threadIdx.x, tx = tid % 16, ty = tid / 16;
    const float* att = g_att + (size_t)b * TT * CCH;
    for (int c0 = 0; c0 < 256; c0 += 16) {
        int row = tid >> 2, cc = (tid & 3) * 4;
        float4 wv = *(const float4*)&w[(o0 + row) * 256 + c0 + cc];
        As[cc + 0][row] = wv.x; As[cc + 1][row] = wv.y;
        As[cc + 2][row] = wv.z; As[cc + 3][row] = wv.w;
        float4 av = *(const float4*)&att[(i0 + row) * 256 + c0 + cc];
        Bs[cc + 0][row] = av.x; Bs[cc + 1][row] = av.y;
        Bs[cc + 2][row] = av.z; Bs[cc + 3][row] = av.w;
        __syncthreads();
#pragma unroll
        for (int kk = 0; kk < 16; kk++) {
            float a[4], bv[4];
            *(float4*)a  = *(const float4*)&As[kk][ty * 4];
            *(float4*)bv = *(const float4*)&Bs[kk][tx * 4];
#pragma unroll
            for (int r = 0; r < 4; r++)
#pragma unroll
                for (int s = 0; s < 4; s++) acc[r][s] += a[r] * bv[s];
        }
        __syncthreads();
    }
#pragma unroll
    for (int r = 0; r < 4; r++) {
        int o = o0 + ty * 4 + r;
        float bv = bias[o];
        float4 xv = *(const float4*)&x[((size_t)b * CCH + o) * TT + i0 + tx * 4];
        *(float4*)&g_y[((size_t)b * CCH + o) * TT + i0 + tx * 4] =
            make_float4(acc[r][0] + bv + xv.x, acc[r][1] + bv + xv.y,
                        acc[r][2] + bv + xv.z, acc[r][3] + bv + xv.w);
    }
}

__global__ void k5_gnstats() {
    int bid = blockIdx.x, b = bid >> 4, g = bid & 15;
    const float* yp = g_y + ((size_t)(b * CCH + g * 16)) * TT;
    int tid = threadIdx.x;
    float s = 0.f, sq = 0.f;
    for (int idx = tid; idx < 16 * TT; idx += 256) { float v = yp[idx]; s += v; sq += v * v; }
#pragma unroll
    for (int off = 16; off > 0; off >>= 1) {
        s  += __shfl_down_sync(0xffffffffu, s, off);
        sq += __shfl_down_sync(0xffffffffu, sq, off);
    }
    __shared__ float rs[8], rq[8];
    if ((tid & 31) == 0) { rs[tid >> 5] = s; rq[tid >> 5] = sq; }
    __syncthreads();
    if (tid == 0) {
        float S = 0.f, Q = 0.f;
#pragma unroll
        for (int w = 0; w < 8; w++) { S += rs[w]; Q += rq[w]; }
        float mu = S / 9216.f;
        float var = Q / 9216.f - mu * mu;
        g_mu[bid] = mu;
        g_rstd[bid] = rsqrtf(var + GN_EPS);
    }
}

__global__ void k6_gnapply(float* __restrict__ out, const float* __restrict__ gw,
                           const float* __restrict__ gb) {
    int idx = blockIdx.x * 256 + threadIdx.x;
    int o = (idx / TT) & 255;
    int b = idx / (TT * CCH);
    float mu = g_mu[b * 16 + (o >> 4)], rstd = g_rstd[b * 16 + (o >> 4)];
    out[idx] = (g_y[idx] - mu) * rstd * gw[o] + gb[o];
}

extern "C" void kernel_launch(void* const* d_in, const int* in_sizes, int n_in,
                              void* d_out, int out_size) {
    const float* x     = (const float*)d_in[0];
    const float* qkv_w = (const float*)d_in[1];
    const float* qkv_b = (const float*)d_in[2];
    const float* rh_k  = (const float*)d_in[3];
    const float* rw_k  = (const float*)d_in[4];
    const float* rh_v  = (const float*)d_in[5];
    const float* rw_v  = (const float*)d_in[6];
    const float* fc_w  = (const float*)d_in[7];
    const float* fc_b  = (const float*)d_in[8];
    const float* gn_w  = (const float*)d_in[9];
    const float* gn_b  = (const float*)d_in[10];
    float* out = (float*)d_out;

    cudaFuncSetAttribute(k2_bd2, cudaFuncAttributeMaxDynamicSharedMemorySize, 49632);
    cudaFuncSetAttribute(k3_attn, cudaFuncAttributeMaxDynamicSharedMemorySize, 61952);

    k0_prep<<<95, 256>>>(rh_v, rw_v, rh_k, rw_k);
    k1_qkv<<<dim3(9, 12, BB), 256>>>(x, qkv_w, qkv_b);
    k1b_transpose<<<dim3(18, NH, BB), dim3(32, 8)>>>();
    k2_bd2<<<dim3(18, BB), 256, 49632>>>();
    k3_attn<<<dim3(36, BB), 256, 61952>>>();
    k4_fc<<<dim3(9, 4, BB), 256>>>(x, fc_w, fc_b);
    k5_gnstats<<<256, 256>>>();
    k6_gnapply<<<9216, 256>>>(out, gn_w, gn_b);
}

// round 6
// speedup vs baseline: 1.3679x; 1.0163x over previous
#include <cuda_runtime.h>
#include <math.h>

#define BB 16
#define CCH 256
#define TT 576
#define NH 8
#define QSCALE 0.17677669529663687f
#define GN_EPS 1e-5f

__device__ float g_qt[BB * NH * TT * 32];
__device__ float g_kt[BB * NH * TT * 32];
__device__ float g_vt[BB * NH * TT * 32];
__device__ float g_E[BB * NH * TT * 48];
__device__ float g_P[48 * 256];
__device__ float g_R[NH * 47 * 32];
__device__ float g_att[BB * TT * CCH];
__device__ float g_y[BB * CCH * TT];
__device__ float g_mu[BB * 16];
__device__ float g_rstd[BB * 16];

// ---------- k0: P table (48x256) + R table (8x47x32) ----------
__global__ void k0_prep(const float* __restrict__ rh_v, const float* __restrict__ rw_v,
                        const float* __restrict__ rh_k, const float* __restrict__ rw_k) {
    int bx = blockIdx.x, tid = threadIdx.x;
    if (bx < 48) {
        int idx = bx * 256 + tid;
        int m = idx >> 8, rest = idx & 255;
        g_P[idx] = (m > 0) ? (rh_v[(m - 1) * 256 + rest] + rw_v[(m - 1) * 256 + rest]) : 0.f;
    } else {
        int l = bx - 48;                 // 0..46
        int n = tid >> 5, d = tid & 31;
        g_R[(n * 47 + l) * 32 + d] = rh_k[(l * 8 + n) * 32 + d] + rw_k[(l * 8 + n) * 32 + d];
    }
}

// ---------- k1: qkv GEMM 64x64 tile, fused transpose epilogue ----------
// writes q,k,v directly into [b][n][t][d] layout (g_qt/g_kt/g_vt)
__global__ __launch_bounds__(256) void k1_qkv(const float* __restrict__ x,
                                              const float* __restrict__ w,
                                              const float* __restrict__ bias) {
    int b = blockIdx.z, o0 = blockIdx.y * 64, i0 = blockIdx.x * 64;
    __shared__ float As[16][68], Bs[16][68];
    __shared__ float Ts[64][68];
    float acc[4][4] = {};
    int tid = threadIdx.x, tx = tid % 16, ty = tid / 16;
    const float* xb = x + (size_t)b * CCH * TT;
    for (int c0 = 0; c0 < 256; c0 += 16) {
        int row = tid >> 2, cc = (tid & 3) * 4;
        float4 wv = *(const float4*)&w[(o0 + row) * 256 + c0 + cc];
        As[cc + 0][row] = wv.x; As[cc + 1][row] = wv.y;
        As[cc + 2][row] = wv.z; As[cc + 3][row] = wv.w;
        int cr = tid >> 4, i4 = (tid & 15) * 4;
        *(float4*)&Bs[cr][i4] = *(const float4*)&xb[(c0 + cr) * TT + i0 + i4];
        __syncthreads();
#pragma unroll
        for (int kk = 0; kk < 16; kk++) {
            float a[4], bv[4];
            *(float4*)a  = *(const float4*)&As[kk][ty * 4];
            *(float4*)bv = *(const float4*)&Bs[kk][tx * 4];
#pragma unroll
            for (int r = 0; r < 4; r++)
#pragma unroll
                for (int s = 0; s < 4; s++) acc[r][s] += a[r] * bv[s];
        }
        __syncthreads();
    }
    // stage transposed (t-major) with bias added
#pragma unroll
    for (int r = 0; r < 4; r++) {
        float bv = bias[o0 + ty * 4 + r];
#pragma unroll
        for (int s = 0; s < 4; s++) Ts[tx * 4 + s][ty * 4 + r] = acc[r][s] + bv;
    }
    __syncthreads();
    int sec = o0 >> 8;                      // 0=q, 1=k, 2=v
    int h0 = (o0 & 255) >> 5;               // first head of this o-tile
    float* dst = (sec == 0) ? g_qt : (sec == 1) ? g_kt : g_vt;
    int tl_ = tid >> 2, quad = tid & 3;     // t_local 0..63, o-quarter
#pragma unroll
    for (int k4 = 0; k4 < 4; k4++) {
        int ol = quad * 16 + k4 * 4;
        int head = h0 + (ol >> 5);
        int d = ol & 31;
        float4 v = *(const float4*)&Ts[tl_][ol];
        *(float4*)&dst[(((size_t)b * NH + head) * TT + i0 + tl_) * 32 + d] = v;
    }
}

// ---------- kE: E[bn][iu][l] = qt[bn][iu]·R[n][l], dense GEMM ----------
__global__ __launch_bounds__(256) void kE_gemm() {
    __shared__ float Qs[64][36];
    __shared__ float Rs[48][36];
    int bn = blockIdx.y;                    // b*8+n, 0..127
    int iu0 = blockIdx.x * 64;
    int n = bn & 7;
    int tid = threadIdx.x;
    const float* qsrc = g_qt + ((size_t)bn * TT + iu0) * 32;
    for (int idx = tid; idx < 64 * 32; idx += 256) {
        Qs[idx >> 5][idx & 31] = qsrc[idx];
    }
    for (int idx = tid; idx < 48 * 32; idx += 256) {
        int r = idx >> 5, d = idx & 31;
        Rs[r][d] = (r < 47) ? g_R[(n * 47 + r) * 32 + d] : 0.f;
    }
    __syncthreads();
    int tl = tid & 15, tiu = tid >> 4;      // 16 l-groups x 16 iu-groups
    float acc[4][3] = {};
#pragma unroll
    for (int d4 = 0; d4 < 8; d4++) {
        float4 q4[4], r4[3];
#pragma unroll
        for (int r = 0; r < 4; r++) q4[r] = *(const float4*)&Qs[tiu * 4 + r][d4 * 4];
#pragma unroll
        for (int j = 0; j < 3; j++) r4[j] = *(const float4*)&Rs[tl * 3 + j][d4 * 4];
#pragma unroll
        for (int r = 0; r < 4; r++)
#pragma unroll
            for (int j = 0; j < 3; j++)
                acc[r][j] += q4[r].x * r4[j].x + q4[r].y * r4[j].y +
                             q4[r].z * r4[j].z + q4[r].w * r4[j].w;
    }
    float* ep = g_E + ((size_t)bn * TT + iu0) * 48;
#pragma unroll
    for (int r = 0; r < 4; r++)
#pragma unroll
        for (int j = 0; j < 3; j++)
            ep[(tiu * 4 + r) * 48 + tl * 3 + j] = acc[r][j];
}

// ---------- k3: fused attention (bd gathered from E) ----------
__global__ __launch_bounds__(256) void k3_attn() {
    extern __shared__ float sm[];
    float* q_s  = sm;            // [8][16][32]   4096
    float* z_s  = sm + 4096;     // [8][32][20]   5120
    float* A_s  = sm + 9216;     // [8][16][25]   3200
    float* bd_s = sm + 12416;    // [8][16][24]   3072
    int b = blockIdx.y, i0 = blockIdx.x * 16;
    int tid = threadIdx.x, warp = tid >> 5, lane = tid & 31;

    {   // coalesced q tile load
        const float* qt = g_qt + (((size_t)b * NH + warp) * TT + i0) * 32;
#pragma unroll
        for (int ii = 0; ii < 16; ii++) q_s[(warp * 16 + ii) * 32 + lane] = qt[ii * 32 + lane];
    }
    for (int idx = tid; idx < 8 * 16 * 24; idx += 256) {
        int n = idx / 384, r = idx % 384, ii = r / 24, c = r % 24;
        int ig = i0 + ii;
        int diff = c - ig;
        int fl = (diff >= 0) ? 0 : -((-diff + 47) / 48);
        int l = diff - 48 * fl;
        int iu = 12 + ig + fl;
        bd_s[idx] = l ? g_E[(((size_t)b * NH + n) * TT + iu) * 48 + (l - 1)] : 0.f;
    }
    for (int idx = tid; idx < 8 * 16 * 25; idx += 256) A_s[idx] = 0.f;

    float acc[16];
#pragma unroll
    for (int ii = 0; ii < 16; ii++) acc[ii] = 0.f;
    __syncthreads();

    for (int jt = 0; jt < TT; jt += 32) {
        {   // logits: warp = head n, lane = j
            int n = warp, j = jt + lane, c = j % 24;
            const float4* kp = (const float4*)(g_kt + (((size_t)b * NH + n) * TT + j) * 32);
            float4 kr[8];
#pragma unroll
            for (int q4 = 0; q4 < 8; q4++) kr[q4] = kp[q4];
#pragma unroll
            for (int ii = 0; ii < 16; ii++) {
                const float4* qv = (const float4*)&q_s[(n * 16 + ii) * 32];
                float s = 0.f;
#pragma unroll
                for (int q4 = 0; q4 < 8; q4++) {
                    float4 qq = qv[q4];
                    s += qq.x * kr[q4].x + qq.y * kr[q4].y + qq.z * kr[q4].z + qq.w * kr[q4].w;
                }
                z_s[(n * 32 + lane) * 20 + ii] = s + bd_s[(n * 16 + ii) * 24 + c];
            }
        }
        __syncthreads();
        {   // softmax over heads at each (i,j)
            int j = tid & 31, ibase = tid >> 5;
#pragma unroll
            for (int p = 0; p < 2; p++) {
                int i = ibase + 8 * p;
                float zz[8];
#pragma unroll
                for (int n = 0; n < 8; n++) zz[n] = z_s[(n * 32 + j) * 20 + i] * QSCALE;
                float mx = zz[0];
#pragma unroll
                for (int n = 1; n < 8; n++) mx = fmaxf(mx, zz[n]);
                float e[8], s = 0.f;
#pragma unroll
                for (int n = 0; n < 8; n++) { e[n] = __expf(zz[n] - mx); s += e[n]; }
                float inv = 1.f / s;
#pragma unroll
                for (int n = 0; n < 8; n++) z_s[(n * 32 + j) * 20 + i] = e[n] * inv;
            }
        }
        __syncthreads();
        {   // A-sums: owner RMW per head-warp (j and j+24 share c)
            int n = warp, c = (jt + lane) % 24;
            if (lane < 24) {
#pragma unroll
                for (int ii = 0; ii < 16; ii++)
                    A_s[(n * 16 + ii) * 25 + c] += z_s[(n * 32 + lane) * 20 + ii];
            }
            __syncwarp();
            if (lane >= 24) {
#pragma unroll
                for (int ii = 0; ii < 16; ii++)
                    A_s[(n * 16 + ii) * 25 + c] += z_s[(n * 32 + lane) * 20 + ii];
            }
        }
        {   // attn @ v: warp = head n, lane = d
            int n = warp, d = lane;
            const float* vp = g_vt + (((size_t)b * NH + n) * TT + jt) * 32 + d;
#pragma unroll 4
            for (int jj = 0; jj < 32; jj++) {
                float v = vp[jj * 32];
                const float4* ap = (const float4*)&z_s[(n * 32 + jj) * 20];
#pragma unroll
                for (int q4 = 0; q4 < 4; q4++) {
                    float4 a = ap[q4];
                    acc[q4 * 4 + 0] += a.x * v; acc[q4 * 4 + 1] += a.y * v;
                    acc[q4 * 4 + 2] += a.z * v; acc[q4 * 4 + 3] += a.w * v;
                }
            }
        }
        __syncthreads();
    }
    {   // epilogue: positional-value term
        int n = warp, d = lane;
#pragma unroll
        for (int ii = 0; ii < 16; ii++) {
            int ig = i0 + ii;
            float o2 = 0.f;
#pragma unroll
            for (int c = 0; c < 24; c++) {
                int m = (c - ig) % 48; if (m < 0) m += 48;
                o2 += A_s[(n * 16 + ii) * 25 + c] * g_P[m * 256 + n * 32 + d];
            }
            g_att[((size_t)b * TT + ig) * CCH + n * 32 + d] = acc[ii] + o2;
        }
    }
}

// ---------- k4: fc GEMM + residual ----------
__global__ __launch_bounds__(256) void k4_fc(const float* __restrict__ x,
                                             const float* __restrict__ w,
                                             const float* __restrict__ bias) {
    int b = blockIdx.z, o0 = blockIdx.y * 64, i0 = blockIdx.x * 64;
    __shared__ float As[16][68], Bs[16][68];
    float acc[4][4] = {};
    int tid = threadIdx.x, tx = tid % 16, ty = tid / 16;
    const float* att = g_att + (size_t)b * TT * CCH;
    for (int c0 = 0; c0 < 256; c0 += 16) {
        int row = tid >> 2, cc = (tid & 3) * 4;
        float4 wv = *(const float4*)&w[(o0 + row) * 256 + c0 + cc];
        As[cc + 0][row] = wv.x; As[cc + 1][row] = wv.y;
        As[cc + 2][row] = wv.z; As[cc + 3][row] = wv.w;
        float4 av = *(const float4*)&att[(i0 + row) * 256 + c0 + cc];
        Bs[cc + 0][row] = av.x; Bs[cc + 1][row] = av.y;
        Bs[cc + 2][row] = av.z; Bs[cc + 3][row] = av.w;
        __syncthreads();
#pragma unroll
        for (int kk = 0; kk < 16; kk++) {
            float a[4], bv[4];
            *(float4*)a  = *(const float4*)&As[kk][ty * 4];
            *(float4*)bv = *(const float4*)&Bs[kk][tx * 4];
#pragma unroll
            for (int r = 0; r < 4; r++)
#pragma unroll
                for (int s = 0; s < 4; s++) acc[r][s] += a[r] * bv[s];
        }
        __syncthreads();
    }
#pragma unroll
    for (int r = 0; r < 4; r++) {
        int o = o0 + ty * 4 + r;
        float bv = bias[o];
        float4 xv = *(const float4*)&x[((size_t)b * CCH + o) * TT + i0 + tx * 4];
        *(float4*)&g_y[((size_t)b * CCH + o) * TT + i0 + tx * 4] =
            make_float4(acc[r][0] + bv + xv.x, acc[r][1] + bv + xv.y,
                        acc[r][2] + bv + xv.z, acc[r][3] + bv + xv.w);
    }
}

__global__ void k5_gnstats() {
    int bid = blockIdx.x, b = bid >> 4, g = bid & 15;
    const float* yp = g_y + ((size_t)(b * CCH + g * 16)) * TT;
    int tid = threadIdx.x;
    float s = 0.f, sq = 0.f;
    for (int idx = tid; idx < 16 * TT; idx += 256) { float v = yp[idx]; s += v; sq += v * v; }
#pragma unroll
    for (int off = 16; off > 0; off >>= 1) {
        s  += __shfl_down_sync(0xffffffffu, s, off);
        sq += __shfl_down_sync(0xffffffffu, sq, off);
    }
    __shared__ float rs[8], rq[8];
    if ((tid & 31) == 0) { rs[tid >> 5] = s; rq[tid >> 5] = sq; }
    __syncthreads();
    if (tid == 0) {
        float S = 0.f, Q = 0.f;
#pragma unroll
        for (int w = 0; w < 8; w++) { S += rs[w]; Q += rq[w]; }
        float mu = S / 9216.f;
        float var = Q / 9216.f - mu * mu;
        g_mu[bid] = mu;
        g_rstd[bid] = rsqrtf(var + GN_EPS);
    }
}

__global__ void k6_gnapply(float* __restrict__ out, const float* __restrict__ gw,
                           const float* __restrict__ gb) {
    int idx = blockIdx.x * 256 + threadIdx.x;
    int o = (idx / TT) & 255;
    int b = idx / (TT * CCH);
    float mu = g_mu[b * 16 + (o >> 4)], rstd = g_rstd[b * 16 + (o >> 4)];
    out[idx] = (g_y[idx] - mu) * rstd * gw[o] + gb[o];
}

extern "C" void kernel_launch(void* const* d_in, const int* in_sizes, int n_in,
                              void* d_out, int out_size) {
    const float* x     = (const float*)d_in[0];
    const float* qkv_w = (const float*)d_in[1];
    const float* qkv_b = (const float*)d_in[2];
    const float* rh_k  = (const float*)d_in[3];
    const float* rw_k  = (const float*)d_in[4];
    const float* rh_v  = (const float*)d_in[5];
    const float* rw_v  = (const float*)d_in[6];
    const float* fc_w  = (const float*)d_in[7];
    const float* fc_b  = (const float*)d_in[8];
    const float* gn_w  = (const float*)d_in[9];
    const float* gn_b  = (const float*)d_in[10];
    float* out = (float*)d_out;

    cudaFuncSetAttribute(k3_attn, cudaFuncAttributeMaxDynamicSharedMemorySize, 61952);

    k0_prep<<<95, 256>>>(rh_v, rw_v, rh_k, rw_k);
    k1_qkv<<<dim3(9, 12, BB), 256>>>(x, qkv_w, qkv_b);
    kE_gemm<<<dim3(9, 128), 256>>>();
    k3_attn<<<dim3(36, BB), 256, 61952>>>();
    k4_fc<<<dim3(9, 4, BB), 256>>>(x, fc_w, fc_b);
    k5_gnstats<<<256, 256>>>();
    k6_gnapply<<<9216, 256>>>(out, gn_w, gn_b);
}